// round 1
// baseline (speedup 1.0000x reference)
#include <cuda_runtime.h>
#include <cuda_bf16.h>
#include <cstdint>

// Problem constants (match reference_code)
#define NN 100000
#define NE 1600000
#define FF 128
#define GG 64
#define EPSV 1e-5f

// Output layout (float32, concatenated tuple):
//   h_emb [NN*FF], flat [GG*FF], edge_index [2*NE], edge_weight [NE], batch [NN]
#define OUT_H    ((size_t)0)
#define OUT_FLAT ((size_t)NN * FF)
#define OUT_EI   (OUT_FLAT + (size_t)GG * FF)
#define OUT_EW   (OUT_EI + (size_t)2 * NE)
#define OUT_B    (OUT_EW + (size_t)NE)

// Scratch (device globals; no runtime allocation allowed)
__device__ float g_dis[NN];                   // deg accumulator -> rsqrt(deg)
__device__ float g_norm[NE];                  // per-edge norm coefficient
__device__ float g_xw[(size_t)NN * FF];       // X @ W
__device__ float g_h[(size_t)NN * FF];        // aggregated features (pre-norm)
__device__ int   g_starts[GG + 1];            // graph node-range boundaries
__device__ float g_sum[GG * FF];              // partial feature sums
__device__ float g_sq[GG * FF];               // partial squared sums
__device__ float g_m2[GG * FF];               // mean * mean_scale
__device__ float g_scale[GG * FF];            // gn_weight * rstd
__device__ float g_shift[GG * FF];            // gn_bias - scale * m2

// ---------------------------------------------------------------------------
// 1. degree init (self-loop weight 1.0)
__global__ void k_init_deg() {
    int i = blockIdx.x * blockDim.x + threadIdx.x;
    if (i < NN) g_dis[i] = 1.0f;
}

// 2. accumulate edge weights into degree of dst
__global__ void k_deg(const int* __restrict__ ei, const float* __restrict__ ew) {
    int e = blockIdx.x * blockDim.x + threadIdx.x;
    if (e < NE) atomicAdd(&g_dis[ei[NE + e]], ew[e]);
}

// 3. deg -> rsqrt(deg)  (deg >= 1 always, self-loop guarantees it)
__global__ void k_rsqrt() {
    int i = blockIdx.x * blockDim.x + threadIdx.x;
    if (i < NN) g_dis[i] = rsqrtf(g_dis[i]);
}

// 4. per-edge norm = dis[src] * ew * dis[dst]
__global__ void k_norm(const int* __restrict__ ei, const float* __restrict__ ew) {
    int e = blockIdx.x * blockDim.x + threadIdx.x;
    if (e < NE) {
        int s = ei[e];
        int d = ei[NE + e];
        g_norm[e] = g_dis[s] * ew[e] * g_dis[d];
    }
}

// 5. xw = X @ W  (fp32, 4x4 register tile per thread, cache-resident W)
__global__ void k_gemm(const float* __restrict__ X, const float* __restrict__ W) {
    int col0 = threadIdx.x * 4;                         // 32 tx -> 128 cols
    int r0 = blockIdx.x * 32 + threadIdx.y * 4;         // 8 ty  -> 32 rows/block
    const float* xr = X + (size_t)r0 * FF;
    float acc[4][4] = {};
#pragma unroll 8
    for (int k4 = 0; k4 < FF; k4 += 4) {
        float4 a0 = *(const float4*)(xr + 0 * FF + k4);
        float4 a1 = *(const float4*)(xr + 1 * FF + k4);
        float4 a2 = *(const float4*)(xr + 2 * FF + k4);
        float4 a3 = *(const float4*)(xr + 3 * FF + k4);
        const float* pa0 = (const float*)&a0;
        const float* pa1 = (const float*)&a1;
        const float* pa2 = (const float*)&a2;
        const float* pa3 = (const float*)&a3;
#pragma unroll
        for (int kk = 0; kk < 4; ++kk) {
            float4 w4 = *(const float4*)(W + (size_t)(k4 + kk) * FF + col0);
            float a;
            a = pa0[kk]; acc[0][0] += a * w4.x; acc[0][1] += a * w4.y; acc[0][2] += a * w4.z; acc[0][3] += a * w4.w;
            a = pa1[kk]; acc[1][0] += a * w4.x; acc[1][1] += a * w4.y; acc[1][2] += a * w4.z; acc[1][3] += a * w4.w;
            a = pa2[kk]; acc[2][0] += a * w4.x; acc[2][1] += a * w4.y; acc[2][2] += a * w4.z; acc[2][3] += a * w4.w;
            a = pa3[kk]; acc[3][0] += a * w4.x; acc[3][1] += a * w4.y; acc[3][2] += a * w4.z; acc[3][3] += a * w4.w;
        }
    }
#pragma unroll
    for (int r = 0; r < 4; ++r) {
        float4 o = make_float4(acc[r][0], acc[r][1], acc[r][2], acc[r][3]);
        *(float4*)(g_xw + (size_t)(r0 + r) * FF + col0) = o;
    }
}

// 6. h init = bias + self-loop contribution (dis^2 * xw)
__global__ void k_init_h(const float* __restrict__ b) {
    int idx = blockIdx.x * blockDim.x + threadIdx.x;   // NN*32 threads
    if (idx >= NN * 32) return;
    int i = idx >> 5;
    int f4 = (idx & 31) * 4;
    float d2 = g_dis[i] * g_dis[i];
    float4 x = *(const float4*)(g_xw + (size_t)i * FF + f4);
    float4 bb = *(const float4*)(b + f4);
    float4 o;
    o.x = bb.x + d2 * x.x;
    o.y = bb.y + d2 * x.y;
    o.z = bb.z + d2 * x.z;
    o.w = bb.w + d2 * x.w;
    *(float4*)(g_h + (size_t)i * FF + f4) = o;
}

// 7. edge scatter: h[dst] += norm * xw[src]   (float4 gather + 4 scalar atomics)
__global__ void k_scatter(const int* __restrict__ ei) {
    long long idx = (long long)blockIdx.x * blockDim.x + threadIdx.x;
    if (idx >= (long long)NE * 32) return;
    int e = (int)(idx >> 5);
    int f4 = ((int)idx & 31) * 4;
    int s = ei[e];
    int d = ei[NE + e];
    float nrm = g_norm[e];
    float4 x = *(const float4*)(g_xw + (size_t)s * FF + f4);
    float* hp = g_h + (size_t)d * FF + f4;
    atomicAdd(hp + 0, nrm * x.x);
    atomicAdd(hp + 1, nrm * x.y);
    atomicAdd(hp + 2, nrm * x.z);
    atomicAdd(hp + 3, nrm * x.w);
}

// 8. graph boundaries from sorted batch
__global__ void k_bounds(const int* __restrict__ batch) {
    int i = blockIdx.x * blockDim.x + threadIdx.x;
    if (i >= NN) return;
    int b = batch[i];
    int prev = (i == 0) ? -1 : batch[i - 1];
    for (int g = prev + 1; g <= b; ++g) g_starts[g] = i;
    if (i == NN - 1)
        for (int g = b + 1; g <= GG; ++g) g_starts[g] = NN;
}

// 9. zero stat buffers + flat output region
__global__ void k_zero(float* __restrict__ out_flat) {
    int i = blockIdx.x * blockDim.x + threadIdx.x;
    if (i < GG * FF) {
        g_sum[i] = 0.0f;
        g_sq[i]  = 0.0f;
        out_flat[i] = 0.0f;
    }
}

// 10. chunked partial sums of h per (graph, feature)
__global__ void k_psum() {
    int g = blockIdx.y, c = blockIdx.x, f = threadIdx.x;
    int s = g_starts[g], e = g_starts[g + 1];
    int per = (e - s + gridDim.x - 1) / gridDim.x;
    int i0 = s + c * per;
    int i1 = min(i0 + per, e);
    float acc = 0.0f;
    for (int i = i0; i < i1; ++i) acc += g_h[(size_t)i * FF + f];
    if (i1 > i0) atomicAdd(&g_sum[g * FF + f], acc);
}

// 11. m2 = mean * mean_scale
__global__ void k_mean(const float* __restrict__ ms) {
    int idx = blockIdx.x * blockDim.x + threadIdx.x;
    if (idx >= GG * FF) return;
    int g = idx >> 7, f = idx & 127;
    float cnt = fmaxf((float)(g_starts[g + 1] - g_starts[g]), 1.0f);
    g_m2[idx] = (g_sum[idx] / cnt) * ms[f];
}

// 12. chunked partial squared sums of (h - m2)
__global__ void k_psq() {
    int g = blockIdx.y, c = blockIdx.x, f = threadIdx.x;
    int s = g_starts[g], e = g_starts[g + 1];
    int per = (e - s + gridDim.x - 1) / gridDim.x;
    int i0 = s + c * per;
    int i1 = min(i0 + per, e);
    float m2 = g_m2[g * FF + f];
    float acc = 0.0f;
    for (int i = i0; i < i1; ++i) {
        float d = g_h[(size_t)i * FF + f] - m2;
        acc += d * d;
    }
    if (i1 > i0) atomicAdd(&g_sq[g * FF + f], acc);
}

// 13. fold GraphNorm into per-(g,f) affine: val = h*scale + shift
__global__ void k_affine(const float* __restrict__ gnw, const float* __restrict__ gnb) {
    int idx = blockIdx.x * blockDim.x + threadIdx.x;
    if (idx >= GG * FF) return;
    int g = idx >> 7, f = idx & 127;
    float cnt = fmaxf((float)(g_starts[g + 1] - g_starts[g]), 1.0f);
    float rstd = rsqrtf(g_sq[idx] / cnt + EPSV);
    float sc = gnw[f] * rstd;
    g_scale[idx] = sc;
    g_shift[idx] = gnb[f] - sc * g_m2[idx];
}

// 14. final normalize + ReLU + write h_emb + per-graph max (flat)
__global__ void k_final(float* __restrict__ out_h, float* __restrict__ out_flat) {
    int g = blockIdx.y, c = blockIdx.x, f = threadIdx.x;
    int s = g_starts[g], e = g_starts[g + 1];
    int per = (e - s + gridDim.x - 1) / gridDim.x;
    int i0 = s + c * per;
    int i1 = min(i0 + per, e);
    float sc = g_scale[g * FF + f];
    float sh = g_shift[g * FF + f];
    float m = 0.0f;
    for (int i = i0; i < i1; ++i) {
        float v = fmaxf(fmaf(g_h[(size_t)i * FF + f], sc, sh), 0.0f);
        out_h[(size_t)i * FF + f] = v;
        m = fmaxf(m, v);
    }
    if (i1 > i0) atomicMax((int*)&out_flat[g * FF + f], __float_as_int(m));
}

// 15. echo edge_index / edge_weight / batch (cast int->float)
__global__ void k_tail(const int* __restrict__ ei, const float* __restrict__ ew,
                       const int* __restrict__ batch, float* __restrict__ out) {
    int j = blockIdx.x * blockDim.x + threadIdx.x;
    int M = 2 * NE + NE + NN;
    if (j >= M) return;
    if (j < 2 * NE) {
        out[OUT_EI + j] = (float)ei[j];
    } else if (j < 3 * NE) {
        out[OUT_EW + (j - 2 * NE)] = ew[j - 2 * NE];
    } else {
        out[OUT_B + (j - 3 * NE)] = (float)batch[j - 3 * NE];
    }
}

// ---------------------------------------------------------------------------
extern "C" void kernel_launch(void* const* d_in, const int* in_sizes, int n_in,
                              void* d_out, int out_size) {
    const float* X   = (const float*)d_in[0];
    const int*   ei  = (const int*)d_in[1];
    const int*   bat = (const int*)d_in[2];
    const float* ew  = (const float*)d_in[3];
    const float* W   = (const float*)d_in[4];
    const float* b   = (const float*)d_in[5];
    const float* gnw = (const float*)d_in[6];
    const float* gnb = (const float*)d_in[7];
    const float* gms = (const float*)d_in[8];
    float* out = (float*)d_out;

    const int T = 256;

    k_init_deg<<<(NN + T - 1) / T, T>>>();
    k_deg<<<(NE + T - 1) / T, T>>>(ei, ew);
    k_rsqrt<<<(NN + T - 1) / T, T>>>();
    k_norm<<<(NE + T - 1) / T, T>>>(ei, ew);

    dim3 gblk(32, 8);
    k_gemm<<<NN / 32, gblk>>>(X, W);          // 100000 % 32 == 0

    k_init_h<<<(NN * 32 + T - 1) / T, T>>>(b);

    long long sc_threads = (long long)NE * 32;
    k_scatter<<<(unsigned)((sc_threads + T - 1) / T), T>>>(ei);

    k_bounds<<<(NN + T - 1) / T, T>>>(bat);
    k_zero<<<(GG * FF + T - 1) / T, T>>>(out + OUT_FLAT);

    dim3 sgrid(16, GG);
    k_psum<<<sgrid, FF>>>();
    k_mean<<<(GG * FF + T - 1) / T, T>>>(gms);
    k_psq<<<sgrid, FF>>>();
    k_affine<<<(GG * FF + T - 1) / T, T>>>(gnw, gnb);

    dim3 fgrid(32, GG);
    k_final<<<fgrid, FF>>>(out + OUT_H, out + OUT_FLAT);

    int tailM = 2 * NE + NE + NN;
    k_tail<<<(tailM + T - 1) / T, T>>>(ei, ew, bat, out);
}